// round 16
// baseline (speedup 1.0000x reference)
#include <cuda_runtime.h>
#include <cuda_bf16.h>
#include <cuda_fp16.h>
#include <math.h>
#include <stdint.h>

// ---------------------------------------------------------------------------
// dims fixed for this dataset
#define QLEN   8192
#define NWAY   5
#define DDIM   640
#define INNER  512
#define HEADS  8
#define DH     64
#define MQ     (QLEN * NWAY)   // 40960
#define MK     QLEN            // 8192

#define LN_BLOCKS  ((MQ + 2 * MK) / 8)          // 7168
#define WP_BLOCKS  ((2 * DDIM * INNER) / 256)   // 2560

// ------------------------- scratch (device globals) ------------------------
__device__ __align__(256) __half g_fk[(size_t)MK * INNER];   // fp16 f_k
__device__ __align__(256) float g_R  [(size_t)MQ * HEADS * 3];   // S1,S2,S3
__device__ __align__(256) float g_kst[(size_t)MK * HEADS * 3];   // mk,nk,vark
__device__ __align__(256) __half g_qhh[(size_t)MQ * DDIM];   // fp16 hi LN(q)
__device__ __align__(256) __half g_qhl[(size_t)MQ * DDIM];   // fp16 lo LN(q)
__device__ __align__(256) __half g_khh[(size_t)MK * DDIM];
__device__ __align__(256) __half g_khl[(size_t)MK * DDIM];
__device__ __align__(256) __half g_vhf[(size_t)MK * DDIM];   // fp16 LN(v)
__device__ __align__(256) __half g_fvh[(size_t)MK * INNER];  // fp16 f_v
__device__ __align__(256) __half g_G  [(size_t)MK * HEADS * DDIM]; // (q,h,d)
__device__ __align__(256) __half g_wi_fh[(size_t)DDIM * INNER];  // fp16 hi W_in
__device__ __align__(256) __half g_wi_fl[(size_t)DDIM * INNER];  // fp16 lo W_in
__device__ __align__(256) __half g_wo_f [(size_t)INNER * DDIM];  // fp16 W_out

// ------------------------- helpers -----------------------------------------
__device__ __forceinline__ uint32_t smem_u32(const void* p) {
    uint32_t a;
    asm("{ .reg .u64 t; cvta.to.shared.u64 t, %1; cvt.u32.u64 %0, t; }"
        : "=r"(a) : "l"(p));
    return a;
}
__device__ __forceinline__ void cp16(uint32_t dst, const void* src) {
    asm volatile(
        "{ .reg .u64 g; cvta.to.global.u64 g, %1;"
        " cp.async.cg.shared.global [%0], [g], 16; }"
        :: "r"(dst), "l"(src) : "memory");
}
__device__ __forceinline__ void cp_commit() {
    asm volatile("cp.async.commit_group;" ::: "memory");
}
__device__ __forceinline__ void cp_wait0() {
    asm volatile("cp.async.wait_group 0;" ::: "memory");
}
template <int N>
__device__ __forceinline__ void cp_waitg() {
    asm volatile("cp.async.wait_group %0;" :: "n"(N) : "memory");
}
__device__ __forceinline__ void ldsm_x4(uint32_t* r, uint32_t addr) {
    asm volatile("ldmatrix.sync.aligned.m8n8.x4.shared.b16 {%0,%1,%2,%3}, [%4];"
                 : "=r"(r[0]), "=r"(r[1]), "=r"(r[2]), "=r"(r[3]) : "r"(addr));
}
__device__ __forceinline__ void ldsm_x4t(uint32_t* r, uint32_t addr) {
    asm volatile("ldmatrix.sync.aligned.m8n8.x4.trans.shared.b16 {%0,%1,%2,%3}, [%4];"
                 : "=r"(r[0]), "=r"(r[1]), "=r"(r[2]), "=r"(r[3]) : "r"(addr));
}
__device__ __forceinline__ void mma_fp16(float* c, const uint32_t* a,
                                         uint32_t b0, uint32_t b1) {
    asm volatile(
        "mma.sync.aligned.m16n8k16.row.col.f32.f16.f16.f32 "
        "{%0,%1,%2,%3}, {%4,%5,%6,%7}, {%8,%9}, {%0,%1,%2,%3};"
        : "+f"(c[0]), "+f"(c[1]), "+f"(c[2]), "+f"(c[3])
        : "r"(a[0]), "r"(a[1]), "r"(a[2]), "r"(a[3]), "r"(b0), "r"(b1));
}
__device__ __forceinline__ void st8h(__half* p, __half a, __half b,
                                     __half c, __half d) {
    __half2 lo = __halves2half2(a, b), hi = __halves2half2(c, d);
    uint2 u;
    u.x = *reinterpret_cast<uint32_t*>(&lo);
    u.y = *reinterpret_cast<uint32_t*>(&hi);
    *reinterpret_cast<uint2*>(p) = u;
}

// ------------------------- fused LN (q,k,v) + W prep ------------------------
__global__ __launch_bounds__(256) void prep_all_kernel(
    const float* __restrict__ Q, const float* __restrict__ K,
    const float* __restrict__ V, const float* __restrict__ g,
    const float* __restrict__ b,
    __half* __restrict__ qhh, __half* __restrict__ qhl,
    __half* __restrict__ khh, __half* __restrict__ khl,
    __half* __restrict__ vhf,
    const float* __restrict__ Win, const float* __restrict__ Wout,
    __half* __restrict__ Tfh, __half* __restrict__ Tfl,
    __half* __restrict__ Tof)
{
    if (blockIdx.x >= LN_BLOCKS) {
        int idx = (blockIdx.x - LN_BLOCKS) * 256 + threadIdx.x;
        const int TOT = DDIM * INNER;
        if (idx < TOT) {
            float w = Win[idx];
            __half fh = __float2half(w);
            Tfh[idx] = fh;
            Tfl[idx] = __float2half(w - __half2float(fh));
        } else {
            Tof[idx - TOT] = __float2half(Wout[idx - TOT]);
        }
        return;
    }

    int row  = blockIdx.x * 8 + (threadIdx.x >> 5);
    int lane = threadIdx.x & 31;
    const float* x;
    int seg, lrow;
    if (row < MQ)            { seg = 0; lrow = row;           x = Q + (size_t)lrow * DDIM; }
    else if (row < MQ + MK)  { seg = 1; lrow = row - MQ;      x = K + (size_t)lrow * DDIM; }
    else                     { seg = 2; lrow = row - MQ - MK; x = V + (size_t)lrow * DDIM; }

    const float4* x4 = reinterpret_cast<const float4*>(x);
    float4 vv[5];
    float s = 0.f, s2 = 0.f;
#pragma unroll
    for (int i = 0; i < 5; i++) {
        vv[i] = x4[lane + i * 32];
        s  += vv[i].x + vv[i].y + vv[i].z + vv[i].w;
        s2 += vv[i].x * vv[i].x + vv[i].y * vv[i].y
            + vv[i].z * vv[i].z + vv[i].w * vv[i].w;
    }
#pragma unroll
    for (int o = 16; o > 0; o >>= 1) {
        s  += __shfl_xor_sync(0xffffffffu, s,  o);
        s2 += __shfl_xor_sync(0xffffffffu, s2, o);
    }
    float m   = s * (1.f / DDIM);
    float var = s2 * (1.f / DDIM) - m * m;
    float rs  = rsqrtf(var + 1e-5f);

    const float4* g4 = reinterpret_cast<const float4*>(g);
    const float4* b4 = reinterpret_cast<const float4*>(b);
#pragma unroll
    for (int i = 0; i < 5; i++) {
        int cb = (lane + i * 32) * 4;
        float4 gv = g4[lane + i * 32];
        float4 bv = b4[lane + i * 32];
        float xn0 = (vv[i].x - m) * rs * gv.x + bv.x;
        float xn1 = (vv[i].y - m) * rs * gv.y + bv.y;
        float xn2 = (vv[i].z - m) * rs * gv.z + bv.z;
        float xn3 = (vv[i].w - m) * rs * gv.w + bv.w;
        size_t o0 = (size_t)lrow * DDIM + cb;
        __half h0 = __float2half(xn0), h1 = __float2half(xn1);
        __half h2 = __float2half(xn2), h3 = __float2half(xn3);
        if (seg == 0) {
            st8h(qhh + o0, h0, h1, h2, h3);
            st8h(qhl + o0,
                 __float2half(xn0 - __half2float(h0)),
                 __float2half(xn1 - __half2float(h1)),
                 __float2half(xn2 - __half2float(h2)),
                 __float2half(xn3 - __half2float(h3)));
        } else if (seg == 1) {
            st8h(khh + o0, h0, h1, h2, h3);
            st8h(khl + o0,
                 __float2half(xn0 - __half2float(h0)),
                 __float2half(xn1 - __half2float(h1)),
                 __float2half(xn2 - __half2float(h2)),
                 __float2half(xn3 - __half2float(h3)));
        } else {
            st8h(vhf + o0, h0, h1, h2, h3);
        }
    }
}

// ------------------------- GEMM body (256 threads, 8 warps) -----------------
// CTA tile 128x256, warp tile 64x64 (2m x 4n) in BOTH modes.
// MODE 1: 3-pass fp16 hi/lo split (AlBh + AhBh + AhBl, fp32 acc), 96KB/stage.
// MODE 0: 1-pass fp16, 48KB/stage. 2 stages each.
// EPI 0: plain C write. EPI 1 (MODE1): warp-local S1,S2,S3 -> Rbuf (fp16 fk
//        tile prefetched into the free stage during the last chunk).
// EPI 2 (MODE1): C write + warp-local k-stats -> Rbuf.
template <int KD, int MODE, bool OUTH, int EPI>
__device__ __forceinline__ void gemm_body(
    int bm, int bn,
    const uint16_t* __restrict__ Ah, const uint16_t* __restrict__ Al,
    const uint16_t* __restrict__ Bh, const uint16_t* __restrict__ Bl,
    void* __restrict__ C_,
    const __half* __restrict__ FK, float* __restrict__ Rbuf,
    int lda, int ldb, int ldc, char* smraw)
{
    constexpr int NC     = KD / 64;
    constexpr int ALOFF  = 16384;
    constexpr int BOFF   = (MODE == 1) ? 32768 : 16384;
    constexpr int BLOFF  = 65536;
    constexpr int STG    = (MODE == 1) ? 98304 : 49152;

    const uint32_t sb = (smem_u32(smraw) + 127u) & ~127u;

    const int tid  = threadIdx.x;
    const int lane = tid & 31;
    const int wid  = tid >> 5;
    const int wm   = (wid >> 2) * 64;
    const int wn   = (wid & 3) * 64;

    float acc[4][8][4];
#pragma unroll
    for (int i = 0; i < 4; i++)
#pragma unroll
        for (int j = 0; j < 8; j++)
#pragma unroll
            for (int t = 0; t < 4; t++) acc[i][j][t] = 0.f;

    auto load_stage = [&](int s, int c) {
        const uint32_t base = sb + (uint32_t)s * STG;
        const int kb = c * 64;
#pragma unroll
        for (int u = tid; u < 1024; u += 256) {
            int r = u >> 3, kc = u & 7;
            uint32_t off = (uint32_t)(r * 128 + kc * 16) ^ (uint32_t)((r & 7) << 4);
            const size_t gi = (size_t)(bm + r) * lda + kb + kc * 8;
            cp16(base + off, Ah + gi);
            if (MODE == 1) cp16(base + ALOFF + off, Al + gi);
        }
#pragma unroll
        for (int u = tid; u < 2048; u += 256) {
            int kk = u >> 5, nc = u & 31;
            uint32_t off = (uint32_t)(kk * 512 + nc * 16) ^ (uint32_t)((kk & 7) << 4);
            const size_t gi = (size_t)(kb + kk) * ldb + bn + nc * 8;
            cp16(base + BOFF + off, Bh + gi);
            if (MODE == 1) cp16(base + BLOFF + off, Bl + gi);
        }
        cp_commit();
    };

    load_stage(0, 0);

    const int arow   = wm + (lane & 15);
    const int acol16 = (lane >> 4) * 16;
    const int brow0  = ((lane >> 3) & 1) * 8 + (lane & 7);
    const int bnc    = wn + (lane >> 4) * 8;

    for (int c = 0; c < NC; c++) {
        cp_wait0();
        __syncthreads();
        if (c + 1 < NC) {
            load_stage((c + 1) & 1, c + 1);
        } else if (EPI == 1) {
            // prefetch fp16 fk tile into the free stage (overlaps last chunk)
            const uint32_t fkb = sb + (uint32_t)(NC & 1) * STG;
            const int q0 = bm / 5;
            const int qn = (bm + 127) / 5 - q0 + 1;   // <= 27
            for (int u = tid; u < qn * 32; u += 256) {
                int r = u >> 5, c8 = u & 31;
                cp16(fkb + (uint32_t)(r * 512 + c8 * 16),
                     FK + (size_t)(q0 + r) * INNER + bn + c8 * 8);
            }
            cp_commit();
        }

        const uint32_t base = sb + (uint32_t)(c & 1) * STG;
#pragma unroll
        for (int ks = 0; ks < 4; ks++) {
            uint32_t af[4][4], bf[16];
            if (MODE == 1) {
                // pass 1: Al * Bh
#pragma unroll
                for (int mf = 0; mf < 4; mf++) {
                    int r = arow + mf * 16;
                    uint32_t off = (uint32_t)(r * 128 + ks * 32 + acol16)
                                 ^ (uint32_t)((r & 7) << 4);
                    ldsm_x4(af[mf], base + ALOFF + off);
                }
#pragma unroll
                for (int g2 = 0; g2 < 4; g2++) {
                    int kk = ks * 16 + brow0;
                    int nn = bnc + g2 * 16;
                    uint32_t off = (uint32_t)(kk * 512 + nn * 2)
                                 ^ (uint32_t)((kk & 7) << 4);
                    ldsm_x4t(&bf[g2 * 4], base + BOFF + off);
                }
#pragma unroll
                for (int mf = 0; mf < 4; mf++)
#pragma unroll
                    for (int nf = 0; nf < 8; nf++)
                        mma_fp16(acc[mf][nf], af[mf], bf[nf * 2], bf[nf * 2 + 1]);
                // pass 2: Ah * Bh
#pragma unroll
                for (int mf = 0; mf < 4; mf++) {
                    int r = arow + mf * 16;
                    uint32_t off = (uint32_t)(r * 128 + ks * 32 + acol16)
                                 ^ (uint32_t)((r & 7) << 4);
                    ldsm_x4(af[mf], base + off);
                }
#pragma unroll
                for (int mf = 0; mf < 4; mf++)
#pragma unroll
                    for (int nf = 0; nf < 8; nf++)
                        mma_fp16(acc[mf][nf], af[mf], bf[nf * 2], bf[nf * 2 + 1]);
                // pass 3: Ah * Bl
#pragma unroll
                for (int g2 = 0; g2 < 4; g2++) {
                    int kk = ks * 16 + brow0;
                    int nn = bnc + g2 * 16;
                    uint32_t off = (uint32_t)(kk * 512 + nn * 2)
                                 ^ (uint32_t)((kk & 7) << 4);
                    ldsm_x4t(&bf[g2 * 4], base + BLOFF + off);
                }
#pragma unroll
                for (int mf = 0; mf < 4; mf++)
#pragma unroll
                    for (int nf = 0; nf < 8; nf++)
                        mma_fp16(acc[mf][nf], af[mf], bf[nf * 2], bf[nf * 2 + 1]);
            } else {
#pragma unroll
                for (int mf = 0; mf < 4; mf++) {
                    int r = arow + mf * 16;
                    uint32_t off = (uint32_t)(r * 128 + ks * 32 + acol16)
                                 ^ (uint32_t)((r & 7) << 4);
                    ldsm_x4(af[mf], base + off);
                }
#pragma unroll
                for (int g2 = 0; g2 < 4; g2++) {
                    int kk = ks * 16 + brow0;
                    int nn = bnc + g2 * 16;
                    uint32_t off = (uint32_t)(kk * 512 + nn * 2)
                                 ^ (uint32_t)((kk & 7) << 4);
                    ldsm_x4t(&bf[g2 * 4], base + BOFF + off);
                }
#pragma unroll
                for (int mf = 0; mf < 4; mf++)
#pragma unroll
                    for (int nf = 0; nf < 8; nf++)
                        mma_fp16(acc[mf][nf], af[mf], bf[nf * 2], bf[nf * 2 + 1]);
            }
        }
    }

    // ---- EPI 1: q-path fused reductions, warp-local (no C write) ----
    if (EPI == 1) {
        cp_wait0();        // fk tile arrival
        __syncthreads();
        const char* smal = smraw + (sb - smem_u32(smraw));
        const __half* fk_sm = (const __half*)(smal + (size_t)(NC & 1) * STG);
        const int q0 = bm / 5;

        int qi_[8];
#pragma unroll
        for (int ridx = 0; ridx < 8; ridx++) {
            int grow = bm + wm + (lane >> 2) + (ridx & 1) * 8 + (ridx >> 1) * 16;
            qi_[ridx] = grow / 5 - q0;
        }
        float s1[8], s2[8], s3[8];
#pragma unroll
        for (int i = 0; i < 8; i++) { s1[i] = 0.f; s2[i] = 0.f; s3[i] = 0.f; }
#pragma unroll
        for (int mf = 0; mf < 4; mf++)
#pragma unroll
            for (int nf = 0; nf < 8; nf++)
#pragma unroll
                for (int t = 0; t < 4; t++) {
                    int ridx = mf * 2 + (t >> 1);
                    float a = acc[mf][nf][t];
                    int col = wn + (lane & 3) * 2 + nf * 8 + (t & 1);
                    float kv = __half2float(fk_sm[qi_[ridx] * 256 + col]);
                    s1[ridx] += a;
                    s2[ridx] += a * a;
                    s3[ridx] += a * kv;
                }
#pragma unroll
        for (int r = 0; r < 8; r++)
#pragma unroll
            for (int o = 1; o <= 2; o <<= 1) {
                s1[r] += __shfl_xor_sync(0xffffffffu, s1[r], o);
                s2[r] += __shfl_xor_sync(0xffffffffu, s2[r], o);
                s3[r] += __shfl_xor_sync(0xffffffffu, s3[r], o);
            }
        if ((lane & 3) == 0) {
            const int head = (bn >> 6) + (wid & 3);
#pragma unroll
            for (int r = 0; r < 8; r++) {
                int grow = bm + wm + (lane >> 2) + (r & 1) * 8 + (r >> 1) * 16;
                float* Rp = Rbuf + ((size_t)grow * HEADS + head) * 3;
                Rp[0] = s1[r]; Rp[1] = s2[r]; Rp[2] = s3[r];
            }
        }
        return;
    }

    // ---- normal C write ----
    const int r0 = bm + wm + (lane >> 2);
    const int c0 = bn + wn + (lane & 3) * 2;
    if (OUTH) {
        __half* Ch = (__half*)C_;
#pragma unroll
        for (int mf = 0; mf < 4; mf++)
#pragma unroll
            for (int nf = 0; nf < 8; nf++) {
                int gr0 = r0 + mf * 16;
                int gc  = c0 + nf * 8;
                __half2 v0 = __floats2half2_rn(acc[mf][nf][0], acc[mf][nf][1]);
                __half2 v1 = __floats2half2_rn(acc[mf][nf][2], acc[mf][nf][3]);
                *reinterpret_cast<__half2*>(Ch + (size_t)gr0 * ldc + gc)       = v0;
                *reinterpret_cast<__half2*>(Ch + (size_t)(gr0 + 8) * ldc + gc) = v1;
            }
    } else {
        float* C = (float*)C_;
#pragma unroll
        for (int mf = 0; mf < 4; mf++)
#pragma unroll
            for (int nf = 0; nf < 8; nf++) {
                int gr0 = r0 + mf * 16;
                int gc  = c0 + nf * 8;
                float2 v0 = make_float2(acc[mf][nf][0], acc[mf][nf][1]);
                float2 v1 = make_float2(acc[mf][nf][2], acc[mf][nf][3]);
                *reinterpret_cast<float2*>(C + (size_t)gr0 * ldc + gc)       = v0;
                *reinterpret_cast<float2*>(C + (size_t)(gr0 + 8) * ldc + gc) = v1;
            }
    }

    // ---- EPI 2: warp-local fused k stats (mk, nk, vark) ----
    if (EPI == 2) {
        float s1[8], s2[8];
#pragma unroll
        for (int i = 0; i < 8; i++) { s1[i] = 0.f; s2[i] = 0.f; }
#pragma unroll
        for (int mf = 0; mf < 4; mf++)
#pragma unroll
            for (int nf = 0; nf < 8; nf++)
#pragma unroll
                for (int t = 0; t < 4; t++) {
                    int ridx = mf * 2 + (t >> 1);
                    float a = acc[mf][nf][t];
                    s1[ridx] += a;
                    s2[ridx] += a * a;
                }
#pragma unroll
        for (int r = 0; r < 8; r++)
#pragma unroll
            for (int o = 1; o <= 2; o <<= 1) {
                s1[r] += __shfl_xor_sync(0xffffffffu, s1[r], o);
                s2[r] += __shfl_xor_sync(0xffffffffu, s2[r], o);
            }
        if ((lane & 3) == 0) {
            const int head = (bn >> 6) + (wid & 3);
#pragma unroll
            for (int r = 0; r < 8; r++) {
                int grow = bm + wm + (lane >> 2) + (r & 1) * 8 + (r >> 1) * 16;
                float S1 = s1[r], S2 = s2[r];
                float mk = S1 * (1.f / DH);
                float* Kp = Rbuf + ((size_t)grow * HEADS + head) * 3;
                Kp[0] = mk;
                Kp[1] = sqrtf(S2);
                Kp[2] = S2 * (1.f / DH) - mk * mk;
            }
        }
    }
}

// ------------------------- G body: A-reuse, 5 N-tiles per CTA ---------------
__device__ __forceinline__ void g_body(
    int bm, int z, const uint16_t* __restrict__ FV,
    const uint16_t* __restrict__ WO, __half* __restrict__ G, char* smraw)
{
    const uint32_t sb = (smem_u32(smraw) + 127u) & ~127u;
    const int tid  = threadIdx.x;
    const int lane = tid & 31;
    const int wid  = tid >> 5;
    const int wm   = (wid >> 2) * 64;
    const int wn   = (wid & 3) * 32;

#pragma unroll
    for (int u = tid; u < 1024; u += 256) {
        int r = u >> 3, kc = u & 7;
        uint32_t off = (uint32_t)(r * 128 + kc * 16) ^ (uint32_t)((r & 7) << 4);
        cp16(sb + off, FV + (size_t)(bm + r) * INNER + z * 64 + kc * 8);
    }
    auto loadB = [&](int j) {
#pragma unroll
        for (int u = tid; u < 1024; u += 256) {
            int kk = u >> 4, nc = u & 15;
            uint32_t off = (uint32_t)(kk * 256 + nc * 16) ^ (uint32_t)((kk & 7) << 4);
            cp16(sb + 16384u * (1 + j) + off,
                 WO + (size_t)(z * 64 + kk) * DDIM + j * 128 + nc * 8);
        }
    };
    loadB(0); cp_commit();
    loadB(1); cp_commit();
    loadB(2); cp_commit();
    loadB(3); cp_commit();
    loadB(4); cp_commit();

    const int arow   = wm + (lane & 15);
    const int acol16 = (lane >> 4) * 16;
    const int brow0  = ((lane >> 3) & 1) * 8 + (lane & 7);
    const int bnc    = wn + (lane >> 4) * 8;
    const int r0     = bm + wm + (lane >> 2);
    const int c0     = wn + (lane & 3) * 2;

#pragma unroll
    for (int j = 0; j < 5; j++) {
        switch (j) {
            case 0: cp_waitg<4>(); break;
            case 1: cp_waitg<3>(); break;
            case 2: cp_waitg<2>(); break;
            case 3: cp_waitg<1>(); break;
            default: cp_waitg<0>(); break;
        }
        __syncthreads();

        float acc[4][4][4];
#pragma unroll
        for (int i = 0; i < 4; i++)
#pragma unroll
            for (int n2 = 0; n2 < 4; n2++)
#pragma unroll
                for (int t = 0; t < 4; t++) acc[i][n2][t] = 0.f;

        const uint32_t bbase = sb + 16384u * (1 + j);
#pragma unroll
        for (int ks = 0; ks < 4; ks++) {
            uint32_t af[4][4], bf[8];
#pragma unroll
            for (int mf = 0; mf < 4; mf++) {
                int r = arow + mf * 16;
                uint32_t off = (uint32_t)(r * 128 + ks * 32 + acol16)
                             ^ (uint32_t)((r & 7) << 4);
                ldsm_x4(af[mf], sb + off);
            }
#pragma unroll
            for (int g2 = 0; g2 < 2; g2++) {
                int kk = ks * 16 + brow0;
                int nn = bnc + g2 * 16;
                uint32_t off = (uint32_t)(kk * 256 + nn * 2)
                             ^ (uint32_t)((kk & 7) << 4);
                ldsm_x4t(&bf[g2 * 4], bbase + off);
            }
#pragma unroll
            for (int mf = 0; mf < 4; mf++)
#pragma unroll
                for (int nf = 0; nf < 4; nf++)
                    mma_fp16(acc[mf][nf], af[mf], bf[nf * 2], bf[nf * 2 + 1]);
        }

        __half* Gz = G + (size_t)z * DDIM + j * 128;
#pragma unroll
        for (int mf = 0; mf < 4; mf++)
#pragma unroll
            for (int nf = 0; nf < 4; nf++) {
                int gr0 = r0 + mf * 16;
                int gc  = c0 + nf * 8;
                __half2 v0 = __floats2half2_rn(acc[mf][nf][0], acc[mf][nf][1]);
                __half2 v1 = __floats2half2_rn(acc[mf][nf][2], acc[mf][nf][3]);
                *reinterpret_cast<__half2*>(
                    Gz + (size_t)gr0 * (HEADS * DDIM) + gc) = v0;
                *reinterpret_cast<__half2*>(
                    Gz + (size_t)(gr0 + 8) * (HEADS * DDIM) + gc) = v1;
            }
    }
}

// ------------------------- merged GEMM launches ------------------------------
// kv: ids [0,128): k-projection 128x256 MODE1 -> fp16 fk + fused k-stats;
//     ids [128,256): v-projection 128x256 MODE0 -> fp16 f_v
__global__ __launch_bounds__(256, 1) void kv_gemm_kernel(
    const __half* __restrict__ khh, const __half* __restrict__ khl,
    const __half* __restrict__ wifh, const __half* __restrict__ wifl,
    __half* __restrict__ fk, float* __restrict__ kst,
    const __half* __restrict__ vhf, __half* __restrict__ fvh)
{
    extern __shared__ char sm[];
    const int id = blockIdx.x;
    if (id < 128) {
        const int bm = (id >> 1) * 128;
        const int bn = (id & 1) * 256;
        gemm_body<640, 1, true, 2>(
            bm, bn, (const uint16_t*)khh, (const uint16_t*)khl,
            (const uint16_t*)wifh, (const uint16_t*)wifl,
            fk, nullptr, kst, DDIM, INNER, INNER, sm);
    } else {
        const int gid = id - 128;
        const int bm = (gid >> 1) * 128;
        const int bn = (gid & 1) * 256;
        gemm_body<640, 0, true, 0>(
            bm, bn, (const uint16_t*)vhf, nullptr,
            (const uint16_t*)wifh, nullptr,
            fvh, nullptr, nullptr, DDIM, INNER, INNER, sm);
    }
}

// qg: ids [0,640): q-projection 128x256 MODE1 + fused reductions -> R;
//     ids [640,1152): per-head projected V, A-reuse G body (512 CTAs)
__global__ __launch_bounds__(256, 1) void qg_gemm_kernel(
    const __half* __restrict__ qhh, const __half* __restrict__ qhl,
    const __half* __restrict__ wifh, const __half* __restrict__ wifl,
    const __half* __restrict__ fk, float* __restrict__ R,
    const __half* __restrict__ fvh, const __half* __restrict__ wof,
    __half* __restrict__ G)
{
    extern __shared__ char sm[];
    const int id = blockIdx.x;
    if (id < 640) {
        const int bm = (id >> 1) * 128;
        const int bn = (id & 1) * 256;
        gemm_body<640, 1, false, 1>(
            bm, bn, (const uint16_t*)qhh, (const uint16_t*)qhl,
            (const uint16_t*)wifh, (const uint16_t*)wifl,
            nullptr, fk, R, DDIM, INNER, INNER, sm);
    } else {
        const int gid = id - 640;          // [0,512)
        const int z   = gid >> 6;          // head
        const int bm  = (gid & 63) * 128;  // fv row tile
        g_body(bm, z, (const uint16_t*)fvh, (const uint16_t*)wof, G, sm);
    }
}

// ------------------------- fused combine + output assembly ------------------
__global__ __launch_bounds__(256) void combine_out_kernel(
    const float* __restrict__ R, const float* __restrict__ kst,
    const __half* __restrict__ G, const float* __restrict__ vs_p,
    const float* __restrict__ cs_p, const float* __restrict__ b_out,
    float* __restrict__ out)
{
    const int q    = blockIdx.x;
    const int tid  = threadIdx.x;
    const int h    = tid >> 5;
    const int lane = tid & 31;
    const float vscale = *vs_p;
    const float cscale = *cs_p;

    __shared__ float c_sm[HEADS][NWAY];
    __shared__ __align__(16) __half G_sm[HEADS * DDIM];

    {
        const float4* Gq = reinterpret_cast<const float4*>(G + (size_t)q * HEADS * DDIM);
        float4* Gs = reinterpret_cast<float4*>(G_sm);
#pragma unroll
        for (int i = tid; i < HEADS * DDIM / 8; i += 256) Gs[i] = Gq[i];
    }

    {
        const int n = (lane < NWAY) ? lane : 0;
        const float* Rp = R + (((size_t)q * NWAY + n) * HEADS + h) * 3;
        const float S1 = Rp[0], S2 = Rp[1], S3 = Rp[2];
        const float* kp = kst + ((size_t)q * HEADS + h) * 3;
        const float mk = kp[0], nk = kp[1], vark = kp[2];

        const float mq   = S1 * (1.f / DH);
        const float varq = S2 * (1.f / DH) - mq * mq;
        const float nq   = sqrtf(S2);
        const float cosd = S3 / (nq * nk);
        const float w    = 1.f / (fabsf(vark - varq) + 1e-6f);
        const float dc   = S3 - mk * S1;
        const float cov  = dc * (1.f / (DH + 1e-6f));
        const float sig  = 1.f / (1.f + expf(-cov));
        const float base = cosd + cscale * sig;

        float vwsum = 0.f;
#pragma unroll
        for (int i = 0; i < NWAY; i++)
            vwsum += __shfl_sync(0xffffffffu, w, i);
        const float inv = 1.f / (vwsum + 1e-6f);
        if (lane < NWAY)
            c_sm[h][lane] = base + vscale * w * inv;
    }
    __syncthreads();

    // vectorized assembly: d in chunks of 8 (one uint4 smem read per head)
    float* oq = out + (size_t)q * NWAY * DDIM;
    for (int idx = tid; idx < NWAY * DDIM / 8; idx += 256) {   // 400
        int n  = idx / 80;
        int d8 = (idx - n * 80) * 8;
        float4 o0 = *reinterpret_cast<const float4*>(b_out + d8);
        float4 o1 = *reinterpret_cast<const float4*>(b_out + d8 + 4);
#pragma unroll
        for (int hh = 0; hh < HEADS; hh++) {
            float ch = c_sm[hh][n];
            uint4 gv = *reinterpret_cast<const uint4*>(G_sm + hh * DDIM + d8);
            __half2 p0 = *reinterpret_cast<__half2*>(&gv.x);
            __half2 p1 = *reinterpret_cast<__half2*>(&gv.y);
            __half2 p2 = *reinterpret_cast<__half2*>(&gv.z);
            __half2 p3 = *reinterpret_cast<__half2*>(&gv.w);
            o0.x += ch * __low2float(p0);
            o0.y += ch * __high2float(p0);
            o0.z += ch * __low2float(p1);
            o0.w += ch * __high2float(p1);
            o1.x += ch * __low2float(p2);
            o1.y += ch * __high2float(p2);
            o1.z += ch * __low2float(p3);
            o1.w += ch * __high2float(p3);
        }
        *reinterpret_cast<float4*>(oq + n * DDIM + d8)     = o0;
        *reinterpret_cast<float4*>(oq + n * DDIM + d8 + 4) = o1;
    }
}

// ---------------------------------------------------------------------------
extern "C" void kernel_launch(void* const* d_in, const int* in_sizes, int n_in,
                              void* d_out, int out_size)
{
    const float* q      = (const float*)d_in[0];
    const float* k      = (const float*)d_in[1];
    const float* v      = (const float*)d_in[2];
    const float* ln_g   = (const float*)d_in[3];
    const float* ln_b   = (const float*)d_in[4];
    const float* W_in   = (const float*)d_in[5];
    const float* W_out  = (const float*)d_in[6];
    const float* b_out  = (const float*)d_in[7];
    const float* vscale = (const float*)d_in[8];
    const float* cscale = (const float*)d_in[9];
    float* out = (float*)d_out;

    float *R, *kst;
    __half *fk, *qhh, *qhl, *khh, *khl, *vhf, *fvh, *G, *wifh, *wifl, *wof;
    cudaGetSymbolAddress((void**)&fk,   g_fk);
    cudaGetSymbolAddress((void**)&R,    g_R);
    cudaGetSymbolAddress((void**)&kst,  g_kst);
    cudaGetSymbolAddress((void**)&qhh,  g_qhh);
    cudaGetSymbolAddress((void**)&qhl,  g_qhl);
    cudaGetSymbolAddress((void**)&khh,  g_khh);
    cudaGetSymbolAddress((void**)&khl,  g_khl);
    cudaGetSymbolAddress((void**)&vhf,  g_vhf);
    cudaGetSymbolAddress((void**)&fvh,  g_fvh);
    cudaGetSymbolAddress((void**)&G,    g_G);
    cudaGetSymbolAddress((void**)&wifh, g_wi_fh);
    cudaGetSymbolAddress((void**)&wifl, g_wi_fl);
    cudaGetSymbolAddress((void**)&wof,  g_wo_f);

    const int SMEM = 2 * 98304 + 128;   // 196736 (2-stage, 96KB/stage MODE1)
    cudaFuncSetAttribute((const void*)kv_gemm_kernel,
                         cudaFuncAttributeMaxDynamicSharedMemorySize, SMEM);
    cudaFuncSetAttribute((const void*)qg_gemm_kernel,
                         cudaFuncAttributeMaxDynamicSharedMemorySize, SMEM);

    // 1) fused LN (vectorized) + weight prep in one launch
    prep_all_kernel<<<LN_BLOCKS + WP_BLOCKS, 256>>>(
        q, k, v, ln_g, ln_b, qhh, qhl, khh, khl, vhf,
        W_in, W_out, wifh, wifl, wof);

    // 2) k-projection (fp16 fk + fused k-stats) and v-projection in one launch
    kv_gemm_kernel<<<256, 256, SMEM>>>(
        khh, khl, wifh, wifl, fk, kst, vhf, fvh);

    // 3) q-projection (+ fused combine reductions) and A-reuse G in one launch
    qg_gemm_kernel<<<1152, 256, SMEM>>>(
        qhh, qhl, wifh, wifl, fk, R, fvh, wof, G);

    // 4) fused combine + output assembly (wide smem reads)
    combine_out_kernel<<<QLEN, 256>>>(R, kst, G, vscale, cscale, b_out, out);
}

// round 17
// speedup vs baseline: 1.0147x; 1.0147x over previous
#include <cuda_runtime.h>
#include <cuda_bf16.h>
#include <cuda_fp16.h>
#include <math.h>
#include <stdint.h>

// ---------------------------------------------------------------------------
// dims fixed for this dataset
#define QLEN   8192
#define NWAY   5
#define DDIM   640
#define INNER  512
#define HEADS  8
#define DH     64
#define MQ     (QLEN * NWAY)   // 40960
#define MK     QLEN            // 8192

#define LN_BLOCKS  ((MQ + 2 * MK) / 8)          // 7168
#define WP_BLOCKS  ((2 * DDIM * INNER) / 256)   // 2560

// ------------------------- scratch (device globals) ------------------------
__device__ __align__(256) float g_fk[(size_t)MK * INNER];
__device__ __align__(256) float g_R  [(size_t)MQ * HEADS * 3];   // S1,S2,S3
__device__ __align__(256) float g_kst[(size_t)MK * HEADS * 3];   // mk,nk,vark
__device__ __align__(256) __half g_qhh[(size_t)MQ * DDIM];   // fp16 hi LN(q)
__device__ __align__(256) __half g_qhl[(size_t)MQ * DDIM];   // fp16 lo LN(q)
__device__ __align__(256) __half g_khh[(size_t)MK * DDIM];
__device__ __align__(256) __half g_khl[(size_t)MK * DDIM];
__device__ __align__(256) __half g_vhf[(size_t)MK * DDIM];   // fp16 LN(v)
__device__ __align__(256) __half g_fvh[(size_t)MK * INNER];  // fp16 f_v
__device__ __align__(256) __half g_G  [(size_t)MK * HEADS * DDIM]; // (q,h,d)
__device__ __align__(256) __half g_wi_fh[(size_t)DDIM * INNER];  // fp16 hi W_in
__device__ __align__(256) __half g_wi_fl[(size_t)DDIM * INNER];  // fp16 lo W_in
__device__ __align__(256) __half g_wo_f [(size_t)INNER * DDIM];  // fp16 W_out

// ------------------------- helpers -----------------------------------------
__device__ __forceinline__ uint32_t smem_u32(const void* p) {
    uint32_t a;
    asm("{ .reg .u64 t; cvta.to.shared.u64 t, %1; cvt.u32.u64 %0, t; }"
        : "=r"(a) : "l"(p));
    return a;
}
__device__ __forceinline__ void cp16(uint32_t dst, const void* src) {
    asm volatile(
        "{ .reg .u64 g; cvta.to.global.u64 g, %1;"
        " cp.async.cg.shared.global [%0], [g], 16; }"
        :: "r"(dst), "l"(src) : "memory");
}
__device__ __forceinline__ void cp_commit() {
    asm volatile("cp.async.commit_group;" ::: "memory");
}
__device__ __forceinline__ void cp_wait0() {
    asm volatile("cp.async.wait_group 0;" ::: "memory");
}
template <int N>
__device__ __forceinline__ void cp_waitg() {
    asm volatile("cp.async.wait_group %0;" :: "n"(N) : "memory");
}
__device__ __forceinline__ void ldsm_x4(uint32_t* r, uint32_t addr) {
    asm volatile("ldmatrix.sync.aligned.m8n8.x4.shared.b16 {%0,%1,%2,%3}, [%4];"
                 : "=r"(r[0]), "=r"(r[1]), "=r"(r[2]), "=r"(r[3]) : "r"(addr));
}
__device__ __forceinline__ void ldsm_x4t(uint32_t* r, uint32_t addr) {
    asm volatile("ldmatrix.sync.aligned.m8n8.x4.trans.shared.b16 {%0,%1,%2,%3}, [%4];"
                 : "=r"(r[0]), "=r"(r[1]), "=r"(r[2]), "=r"(r[3]) : "r"(addr));
}
__device__ __forceinline__ void mma_fp16(float* c, const uint32_t* a,
                                         uint32_t b0, uint32_t b1) {
    asm volatile(
        "mma.sync.aligned.m16n8k16.row.col.f32.f16.f16.f32 "
        "{%0,%1,%2,%3}, {%4,%5,%6,%7}, {%8,%9}, {%0,%1,%2,%3};"
        : "+f"(c[0]), "+f"(c[1]), "+f"(c[2]), "+f"(c[3])
        : "r"(a[0]), "r"(a[1]), "r"(a[2]), "r"(a[3]), "r"(b0), "r"(b1));
}
__device__ __forceinline__ void st8h(__half* p, __half a, __half b,
                                     __half c, __half d) {
    __half2 lo = __halves2half2(a, b), hi = __halves2half2(c, d);
    uint2 u;
    u.x = *reinterpret_cast<uint32_t*>(&lo);
    u.y = *reinterpret_cast<uint32_t*>(&hi);
    *reinterpret_cast<uint2*>(p) = u;
}

// ------------------------- fused LN (q,k,v) + W prep ------------------------
__global__ __launch_bounds__(256) void prep_all_kernel(
    const float* __restrict__ Q, const float* __restrict__ K,
    const float* __restrict__ V, const float* __restrict__ g,
    const float* __restrict__ b,
    __half* __restrict__ qhh, __half* __restrict__ qhl,
    __half* __restrict__ khh, __half* __restrict__ khl,
    __half* __restrict__ vhf,
    const float* __restrict__ Win, const float* __restrict__ Wout,
    __half* __restrict__ Tfh, __half* __restrict__ Tfl,
    __half* __restrict__ Tof)
{
    if (blockIdx.x >= LN_BLOCKS) {
        int idx = (blockIdx.x - LN_BLOCKS) * 256 + threadIdx.x;
        const int TOT = DDIM * INNER;
        if (idx < TOT) {
            float w = Win[idx];
            __half fh = __float2half(w);
            Tfh[idx] = fh;
            Tfl[idx] = __float2half(w - __half2float(fh));
        } else {
            Tof[idx - TOT] = __float2half(Wout[idx - TOT]);
        }
        return;
    }

    int row  = blockIdx.x * 8 + (threadIdx.x >> 5);
    int lane = threadIdx.x & 31;
    const float* x;
    int seg, lrow;
    if (row < MQ)            { seg = 0; lrow = row;           x = Q + (size_t)lrow * DDIM; }
    else if (row < MQ + MK)  { seg = 1; lrow = row - MQ;      x = K + (size_t)lrow * DDIM; }
    else                     { seg = 2; lrow = row - MQ - MK; x = V + (size_t)lrow * DDIM; }

    const float4* x4 = reinterpret_cast<const float4*>(x);
    float4 vv[5];
    float s = 0.f, s2 = 0.f;
#pragma unroll
    for (int i = 0; i < 5; i++) {
        vv[i] = x4[lane + i * 32];
        s  += vv[i].x + vv[i].y + vv[i].z + vv[i].w;
        s2 += vv[i].x * vv[i].x + vv[i].y * vv[i].y
            + vv[i].z * vv[i].z + vv[i].w * vv[i].w;
    }
#pragma unroll
    for (int o = 16; o > 0; o >>= 1) {
        s  += __shfl_xor_sync(0xffffffffu, s,  o);
        s2 += __shfl_xor_sync(0xffffffffu, s2, o);
    }
    float m   = s * (1.f / DDIM);
    float var = s2 * (1.f / DDIM) - m * m;
    float rs  = rsqrtf(var + 1e-5f);

    const float4* g4 = reinterpret_cast<const float4*>(g);
    const float4* b4 = reinterpret_cast<const float4*>(b);
#pragma unroll
    for (int i = 0; i < 5; i++) {
        int cb = (lane + i * 32) * 4;
        float4 gv = g4[lane + i * 32];
        float4 bv = b4[lane + i * 32];
        float xn0 = (vv[i].x - m) * rs * gv.x + bv.x;
        float xn1 = (vv[i].y - m) * rs * gv.y + bv.y;
        float xn2 = (vv[i].z - m) * rs * gv.z + bv.z;
        float xn3 = (vv[i].w - m) * rs * gv.w + bv.w;
        size_t o0 = (size_t)lrow * DDIM + cb;
        __half h0 = __float2half(xn0), h1 = __float2half(xn1);
        __half h2 = __float2half(xn2), h3 = __float2half(xn3);
        if (seg == 0) {
            st8h(qhh + o0, h0, h1, h2, h3);
            st8h(qhl + o0,
                 __float2half(xn0 - __half2float(h0)),
                 __float2half(xn1 - __half2float(h1)),
                 __float2half(xn2 - __half2float(h2)),
                 __float2half(xn3 - __half2float(h3)));
        } else if (seg == 1) {
            st8h(khh + o0, h0, h1, h2, h3);
            st8h(khl + o0,
                 __float2half(xn0 - __half2float(h0)),
                 __float2half(xn1 - __half2float(h1)),
                 __float2half(xn2 - __half2float(h2)),
                 __float2half(xn3 - __half2float(h3)));
        } else {
            st8h(vhf + o0, h0, h1, h2, h3);
        }
    }
}

// ------------------------- GEMM body (256 threads, 8 warps) -----------------
// CTA tile 128x256, warp tile 64x64 (2m x 4n) in BOTH modes.
// MODE 1: 3-pass fp16 hi/lo split (AlBh + AhBh + AhBl, fp32 acc), 96KB/stage.
// MODE 0: 1-pass fp16, 48KB/stage. 2 stages each.
// EPI 0: plain C write. EPI 1 (MODE1): warp-local S1,S2,S3 -> Rbuf (fk tile
//        prefetched via cp.async into the free stage during the last chunk).
// EPI 2 (MODE1): C write + warp-local k-stats -> Rbuf.
template <int KD, int MODE, bool OUTH, int EPI>
__device__ __forceinline__ void gemm_body(
    int bm, int bn,
    const uint16_t* __restrict__ Ah, const uint16_t* __restrict__ Al,
    const uint16_t* __restrict__ Bh, const uint16_t* __restrict__ Bl,
    void* __restrict__ C_,
    const float* __restrict__ FK, float* __restrict__ Rbuf,
    int lda, int ldb, int ldc, char* smraw)
{
    constexpr int NC     = KD / 64;
    constexpr int ALOFF  = 16384;
    constexpr int BOFF   = (MODE == 1) ? 32768 : 16384;
    constexpr int BLOFF  = 65536;
    constexpr int STG    = (MODE == 1) ? 98304 : 49152;

    const uint32_t sb = (smem_u32(smraw) + 127u) & ~127u;

    const int tid  = threadIdx.x;
    const int lane = tid & 31;
    const int wid  = tid >> 5;
    const int wm   = (wid >> 2) * 64;
    const int wn   = (wid & 3) * 64;

    float acc[4][8][4];
#pragma unroll
    for (int i = 0; i < 4; i++)
#pragma unroll
        for (int j = 0; j < 8; j++)
#pragma unroll
            for (int t = 0; t < 4; t++) acc[i][j][t] = 0.f;

    auto load_stage = [&](int s, int c) {
        const uint32_t base = sb + (uint32_t)s * STG;
        const int kb = c * 64;
#pragma unroll
        for (int u = tid; u < 1024; u += 256) {
            int r = u >> 3, kc = u & 7;
            uint32_t off = (uint32_t)(r * 128 + kc * 16) ^ (uint32_t)((r & 7) << 4);
            const size_t gi = (size_t)(bm + r) * lda + kb + kc * 8;
            cp16(base + off, Ah + gi);
            if (MODE == 1) cp16(base + ALOFF + off, Al + gi);
        }
#pragma unroll
        for (int u = tid; u < 2048; u += 256) {
            int kk = u >> 5, nc = u & 31;
            uint32_t off = (uint32_t)(kk * 512 + nc * 16) ^ (uint32_t)((kk & 7) << 4);
            const size_t gi = (size_t)(kb + kk) * ldb + bn + nc * 8;
            cp16(base + BOFF + off, Bh + gi);
            if (MODE == 1) cp16(base + BLOFF + off, Bl + gi);
        }
        cp_commit();
    };

    load_stage(0, 0);

    const int arow   = wm + (lane & 15);
    const int acol16 = (lane >> 4) * 16;
    const int brow0  = ((lane >> 3) & 1) * 8 + (lane & 7);
    const int bnc    = wn + (lane >> 4) * 8;

    for (int c = 0; c < NC; c++) {
        cp_wait0();
        __syncthreads();
        if (c + 1 < NC) {
            load_stage((c + 1) & 1, c + 1);
        } else if (EPI == 1) {
            // prefetch fk tile into the free stage (overlaps last chunk)
            const uint32_t fkb = sb + (uint32_t)(NC & 1) * STG;
            const int q0 = bm / 5;
            const int qn = (bm + 127) / 5 - q0 + 1;   // <= 27
            for (int u = tid; u < qn * 64; u += 256) {
                int r = u >> 6, c16 = u & 63;
                cp16(fkb + (uint32_t)(r * 1024 + c16 * 16),
                     FK + (size_t)(q0 + r) * INNER + bn + c16 * 4);
            }
            cp_commit();
        }

        const uint32_t base = sb + (uint32_t)(c & 1) * STG;
#pragma unroll
        for (int ks = 0; ks < 4; ks++) {
            uint32_t af[4][4], bf[16];
            if (MODE == 1) {
                // pass 1: Al * Bh
#pragma unroll
                for (int mf = 0; mf < 4; mf++) {
                    int r = arow + mf * 16;
                    uint32_t off = (uint32_t)(r * 128 + ks * 32 + acol16)
                                 ^ (uint32_t)((r & 7) << 4);
                    ldsm_x4(af[mf], base + ALOFF + off);
                }
#pragma unroll
                for (int g2 = 0; g2 < 4; g2++) {
                    int kk = ks * 16 + brow0;
                    int nn = bnc + g2 * 16;
                    uint32_t off = (uint32_t)(kk * 512 + nn * 2)
                                 ^ (uint32_t)((kk & 7) << 4);
                    ldsm_x4t(&bf[g2 * 4], base + BOFF + off);
                }
#pragma unroll
                for (int mf = 0; mf < 4; mf++)
#pragma unroll
                    for (int nf = 0; nf < 8; nf++)
                        mma_fp16(acc[mf][nf], af[mf], bf[nf * 2], bf[nf * 2 + 1]);
                // pass 2: Ah * Bh
#pragma unroll
                for (int mf = 0; mf < 4; mf++) {
                    int r = arow + mf * 16;
                    uint32_t off = (uint32_t)(r * 128 + ks * 32 + acol16)
                                 ^ (uint32_t)((r & 7) << 4);
                    ldsm_x4(af[mf], base + off);
                }
#pragma unroll
                for (int mf = 0; mf < 4; mf++)
#pragma unroll
                    for (int nf = 0; nf < 8; nf++)
                        mma_fp16(acc[mf][nf], af[mf], bf[nf * 2], bf[nf * 2 + 1]);
                // pass 3: Ah * Bl
#pragma unroll
                for (int g2 = 0; g2 < 4; g2++) {
                    int kk = ks * 16 + brow0;
                    int nn = bnc + g2 * 16;
                    uint32_t off = (uint32_t)(kk * 512 + nn * 2)
                                 ^ (uint32_t)((kk & 7) << 4);
                    ldsm_x4t(&bf[g2 * 4], base + BLOFF + off);
                }
#pragma unroll
                for (int mf = 0; mf < 4; mf++)
#pragma unroll
                    for (int nf = 0; nf < 8; nf++)
                        mma_fp16(acc[mf][nf], af[mf], bf[nf * 2], bf[nf * 2 + 1]);
            } else {
#pragma unroll
                for (int mf = 0; mf < 4; mf++) {
                    int r = arow + mf * 16;
                    uint32_t off = (uint32_t)(r * 128 + ks * 32 + acol16)
                                 ^ (uint32_t)((r & 7) << 4);
                    ldsm_x4(af[mf], base + off);
                }
#pragma unroll
                for (int g2 = 0; g2 < 4; g2++) {
                    int kk = ks * 16 + brow0;
                    int nn = bnc + g2 * 16;
                    uint32_t off = (uint32_t)(kk * 512 + nn * 2)
                                 ^ (uint32_t)((kk & 7) << 4);
                    ldsm_x4t(&bf[g2 * 4], base + BOFF + off);
                }
#pragma unroll
                for (int mf = 0; mf < 4; mf++)
#pragma unroll
                    for (int nf = 0; nf < 8; nf++)
                        mma_fp16(acc[mf][nf], af[mf], bf[nf * 2], bf[nf * 2 + 1]);
            }
        }
    }

    // ---- EPI 1: q-path fused reductions, warp-local (no C write) ----
    if (EPI == 1) {
        cp_wait0();        // fk tile arrival
        __syncthreads();
        const char* smal = smraw + (sb - smem_u32(smraw));
        const float* fk_sm = (const float*)(smal + (size_t)(NC & 1) * STG);
        const int q0 = bm / 5;

        int qi_[8];
#pragma unroll
        for (int ridx = 0; ridx < 8; ridx++) {
            int grow = bm + wm + (lane >> 2) + (ridx & 1) * 8 + (ridx >> 1) * 16;
            qi_[ridx] = grow / 5 - q0;
        }
        float s1[8], s2[8], s3[8];
#pragma unroll
        for (int i = 0; i < 8; i++) { s1[i] = 0.f; s2[i] = 0.f; s3[i] = 0.f; }
#pragma unroll
        for (int mf = 0; mf < 4; mf++)
#pragma unroll
            for (int nf = 0; nf < 8; nf++)
#pragma unroll
                for (int t = 0; t < 4; t++) {
                    int ridx = mf * 2 + (t >> 1);
                    float a = acc[mf][nf][t];
                    int col = wn + (lane & 3) * 2 + nf * 8 + (t & 1);
                    float kv = fk_sm[qi_[ridx] * 256 + col];
                    s1[ridx] += a;
                    s2[ridx] += a * a;
                    s3[ridx] += a * kv;
                }
#pragma unroll
        for (int r = 0; r < 8; r++)
#pragma unroll
            for (int o = 1; o <= 2; o <<= 1) {
                s1[r] += __shfl_xor_sync(0xffffffffu, s1[r], o);
                s2[r] += __shfl_xor_sync(0xffffffffu, s2[r], o);
                s3[r] += __shfl_xor_sync(0xffffffffu, s3[r], o);
            }
        if ((lane & 3) == 0) {
            const int head = (bn >> 6) + (wid & 3);
#pragma unroll
            for (int r = 0; r < 8; r++) {
                int grow = bm + wm + (lane >> 2) + (r & 1) * 8 + (r >> 1) * 16;
                float* Rp = Rbuf + ((size_t)grow * HEADS + head) * 3;
                Rp[0] = s1[r]; Rp[1] = s2[r]; Rp[2] = s3[r];
            }
        }
        return;
    }

    // ---- normal C write ----
    const int r0 = bm + wm + (lane >> 2);
    const int c0 = bn + wn + (lane & 3) * 2;
    if (OUTH) {
        __half* Ch = (__half*)C_;
#pragma unroll
        for (int mf = 0; mf < 4; mf++)
#pragma unroll
            for (int nf = 0; nf < 8; nf++) {
                int gr0 = r0 + mf * 16;
                int gc  = c0 + nf * 8;
                __half2 v0 = __floats2half2_rn(acc[mf][nf][0], acc[mf][nf][1]);
                __half2 v1 = __floats2half2_rn(acc[mf][nf][2], acc[mf][nf][3]);
                *reinterpret_cast<__half2*>(Ch + (size_t)gr0 * ldc + gc)       = v0;
                *reinterpret_cast<__half2*>(Ch + (size_t)(gr0 + 8) * ldc + gc) = v1;
            }
    } else {
        float* C = (float*)C_;
#pragma unroll
        for (int mf = 0; mf < 4; mf++)
#pragma unroll
            for (int nf = 0; nf < 8; nf++) {
                int gr0 = r0 + mf * 16;
                int gc  = c0 + nf * 8;
                float2 v0 = make_float2(acc[mf][nf][0], acc[mf][nf][1]);
                float2 v1 = make_float2(acc[mf][nf][2], acc[mf][nf][3]);
                *reinterpret_cast<float2*>(C + (size_t)gr0 * ldc + gc)       = v0;
                *reinterpret_cast<float2*>(C + (size_t)(gr0 + 8) * ldc + gc) = v1;
            }
    }

    // ---- EPI 2: warp-local fused k stats (mk, nk, vark) ----
    if (EPI == 2) {
        float s1[8], s2[8];
#pragma unroll
        for (int i = 0; i < 8; i++) { s1[i] = 0.f; s2[i] = 0.f; }
#pragma unroll
        for (int mf = 0; mf < 4; mf++)
#pragma unroll
            for (int nf = 0; nf < 8; nf++)
#pragma unroll
                for (int t = 0; t < 4; t++) {
                    int ridx = mf * 2 + (t >> 1);
                    float a = acc[mf][nf][t];
                    s1[ridx] += a;
                    s2[ridx] += a * a;
                }
#pragma unroll
        for (int r = 0; r < 8; r++)
#pragma unroll
            for (int o = 1; o <= 2; o <<= 1) {
                s1[r] += __shfl_xor_sync(0xffffffffu, s1[r], o);
                s2[r] += __shfl_xor_sync(0xffffffffu, s2[r], o);
            }
        if ((lane & 3) == 0) {
            const int head = (bn >> 6) + (wid & 3);
#pragma unroll
            for (int r = 0; r < 8; r++) {
                int grow = bm + wm + (lane >> 2) + (r & 1) * 8 + (r >> 1) * 16;
                float S1 = s1[r], S2 = s2[r];
                float mk = S1 * (1.f / DH);
                float* Kp = Rbuf + ((size_t)grow * HEADS + head) * 3;
                Kp[0] = mk;
                Kp[1] = sqrtf(S2);
                Kp[2] = S2 * (1.f / DH) - mk * mk;
            }
        }
    }
}

// ------------------------- G body: A-reuse, 5 N-tiles per CTA ---------------
__device__ __forceinline__ void g_body(
    int bm, int z, const uint16_t* __restrict__ FV,
    const uint16_t* __restrict__ WO, __half* __restrict__ G, char* smraw)
{
    const uint32_t sb = (smem_u32(smraw) + 127u) & ~127u;
    const int tid  = threadIdx.x;
    const int lane = tid & 31;
    const int wid  = tid >> 5;
    const int wm   = (wid >> 2) * 64;
    const int wn   = (wid & 3) * 32;

#pragma unroll
    for (int u = tid; u < 1024; u += 256) {
        int r = u >> 3, kc = u & 7;
        uint32_t off = (uint32_t)(r * 128 + kc * 16) ^ (uint32_t)((r & 7) << 4);
        cp16(sb + off, FV + (size_t)(bm + r) * INNER + z * 64 + kc * 8);
    }
    auto loadB = [&](int j) {
#pragma unroll
        for (int u = tid; u < 1024; u += 256) {
            int kk = u >> 4, nc = u & 15;
            uint32_t off = (uint32_t)(kk * 256 + nc * 16) ^ (uint32_t)((kk & 7) << 4);
            cp16(sb + 16384u * (1 + j) + off,
                 WO + (size_t)(z * 64 + kk) * DDIM + j * 128 + nc * 8);
        }
    };
    loadB(0); cp_commit();
    loadB(1); cp_commit();
    loadB(2); cp_commit();
    loadB(3); cp_commit();
    loadB(4); cp_commit();

    const int arow   = wm + (lane & 15);
    const int acol16 = (lane >> 4) * 16;
    const int brow0  = ((lane >> 3) & 1) * 8 + (lane & 7);
    const int bnc    = wn + (lane >> 4) * 8;
    const int r0     = bm + wm + (lane >> 2);
    const int c0     = wn + (lane & 3) * 2;

#pragma unroll
    for (int j = 0; j < 5; j++) {
        switch (j) {
            case 0: cp_waitg<4>(); break;
            case 1: cp_waitg<3>(); break;
            case 2: cp_waitg<2>(); break;
            case 3: cp_waitg<1>(); break;
            default: cp_waitg<0>(); break;
        }
        __syncthreads();

        float acc[4][4][4];
#pragma unroll
        for (int i = 0; i < 4; i++)
#pragma unroll
            for (int n2 = 0; n2 < 4; n2++)
#pragma unroll
                for (int t = 0; t < 4; t++) acc[i][n2][t] = 0.f;

        const uint32_t bbase = sb + 16384u * (1 + j);
#pragma unroll
        for (int ks = 0; ks < 4; ks++) {
            uint32_t af[4][4], bf[8];
#pragma unroll
            for (int mf = 0; mf < 4; mf++) {
                int r = arow + mf * 16;
                uint32_t off = (uint32_t)(r * 128 + ks * 32 + acol16)
                             ^ (uint32_t)((r & 7) << 4);
                ldsm_x4(af[mf], sb + off);
            }
#pragma unroll
            for (int g2 = 0; g2 < 2; g2++) {
                int kk = ks * 16 + brow0;
                int nn = bnc + g2 * 16;
                uint32_t off = (uint32_t)(kk * 256 + nn * 2)
                             ^ (uint32_t)((kk & 7) << 4);
                ldsm_x4t(&bf[g2 * 4], bbase + off);
            }
#pragma unroll
            for (int mf = 0; mf < 4; mf++)
#pragma unroll
                for (int nf = 0; nf < 4; nf++)
                    mma_fp16(acc[mf][nf], af[mf], bf[nf * 2], bf[nf * 2 + 1]);
        }

        __half* Gz = G + (size_t)z * DDIM + j * 128;
#pragma unroll
        for (int mf = 0; mf < 4; mf++)
#pragma unroll
            for (int nf = 0; nf < 4; nf++) {
                int gr0 = r0 + mf * 16;
                int gc  = c0 + nf * 8;
                __half2 v0 = __floats2half2_rn(acc[mf][nf][0], acc[mf][nf][1]);
                __half2 v1 = __floats2half2_rn(acc[mf][nf][2], acc[mf][nf][3]);
                *reinterpret_cast<__half2*>(
                    Gz + (size_t)gr0 * (HEADS * DDIM) + gc) = v0;
                *reinterpret_cast<__half2*>(
                    Gz + (size_t)(gr0 + 8) * (HEADS * DDIM) + gc) = v1;
            }
    }
}

// ------------------------- merged GEMM launches ------------------------------
// kv: ids [0,128): k-projection 128x256 MODE1 + fused k-stats;
//     ids [128,256): v-projection 128x256 MODE0 -> fp16 f_v
__global__ __launch_bounds__(256, 1) void kv_gemm_kernel(
    const __half* __restrict__ khh, const __half* __restrict__ khl,
    const __half* __restrict__ wifh, const __half* __restrict__ wifl,
    float* __restrict__ fk, float* __restrict__ kst,
    const __half* __restrict__ vhf, __half* __restrict__ fvh)
{
    extern __shared__ char sm[];
    const int id = blockIdx.x;
    if (id < 128) {
        const int bm = (id >> 1) * 128;
        const int bn = (id & 1) * 256;
        gemm_body<640, 1, false, 2>(
            bm, bn, (const uint16_t*)khh, (const uint16_t*)khl,
            (const uint16_t*)wifh, (const uint16_t*)wifl,
            fk, nullptr, kst, DDIM, INNER, INNER, sm);
    } else {
        const int gid = id - 128;
        const int bm = (gid >> 1) * 128;
        const int bn = (gid & 1) * 256;
        gemm_body<640, 0, true, 0>(
            bm, bn, (const uint16_t*)vhf, nullptr,
            (const uint16_t*)wifh, nullptr,
            fvh, nullptr, nullptr, DDIM, INNER, INNER, sm);
    }
}

// qg: ids [0,640): q-projection 128x256 MODE1 + fused reductions -> R;
//     ids [640,1152): per-head projected V, A-reuse G body (512 CTAs)
__global__ __launch_bounds__(256, 1) void qg_gemm_kernel(
    const __half* __restrict__ qhh, const __half* __restrict__ qhl,
    const __half* __restrict__ wifh, const __half* __restrict__ wifl,
    const float* __restrict__ fk, float* __restrict__ R,
    const __half* __restrict__ fvh, const __half* __restrict__ wof,
    __half* __restrict__ G)
{
    extern __shared__ char sm[];
    const int id = blockIdx.x;
    if (id < 640) {
        const int bm = (id >> 1) * 128;
        const int bn = (id & 1) * 256;
        gemm_body<640, 1, false, 1>(
            bm, bn, (const uint16_t*)qhh, (const uint16_t*)qhl,
            (const uint16_t*)wifh, (const uint16_t*)wifl,
            nullptr, fk, R, DDIM, INNER, INNER, sm);
    } else {
        const int gid = id - 640;          // [0,512)
        const int z   = gid >> 6;          // head
        const int bm  = (gid & 63) * 128;  // fv row tile
        g_body(bm, z, (const uint16_t*)fvh, (const uint16_t*)wof, G, sm);
    }
}

// ------------------------- fused combine + output assembly ------------------
// Phase 1: warps compute c[h][n]. Phase 2: 160 threads each own one d4 chunk;
// read G[q][hh][d4] from GLOBAL once (uint2, coalesced) and accumulate into
// 5 float4 register accumulators (n-reuse) -> no G smem staging at all.
__global__ __launch_bounds__(256) void combine_out_kernel(
    const float* __restrict__ R, const float* __restrict__ kst,
    const __half* __restrict__ G, const float* __restrict__ vs_p,
    const float* __restrict__ cs_p, const float* __restrict__ b_out,
    float* __restrict__ out)
{
    const int q    = blockIdx.x;
    const int tid  = threadIdx.x;
    const int h    = tid >> 5;
    const int lane = tid & 31;
    const float vscale = *vs_p;
    const float cscale = *cs_p;

    __shared__ float c_sm[HEADS][NWAY];

    {
        const int n = (lane < NWAY) ? lane : 0;
        const float* Rp = R + (((size_t)q * NWAY + n) * HEADS + h) * 3;
        const float S1 = Rp[0], S2 = Rp[1], S3 = Rp[2];
        const float* kp = kst + ((size_t)q * HEADS + h) * 3;
        const float mk = kp[0], nk = kp[1], vark = kp[2];

        const float mq   = S1 * (1.f / DH);
        const float varq = S2 * (1.f / DH) - mq * mq;
        const float nq   = sqrtf(S2);
        const float cosd = S3 / (nq * nk);
        const float w    = 1.f / (fabsf(vark - varq) + 1e-6f);
        const float dc   = S3 - mk * S1;
        const float cov  = dc * (1.f / (DH + 1e-6f));
        const float sig  = 1.f / (1.f + expf(-cov));
        const float base = cosd + cscale * sig;

        float vwsum = 0.f;
#pragma unroll
        for (int i = 0; i < NWAY; i++)
            vwsum += __shfl_sync(0xffffffffu, w, i);
        const float inv = 1.f / (vwsum + 1e-6f);
        if (lane < NWAY)
            c_sm[h][lane] = base + vscale * w * inv;
    }
    __syncthreads();

    // phase 2: 160 threads, one d4 chunk each, all 5 n in registers
    if (tid < 160) {
        const int d4 = tid * 4;
        float c_r[HEADS][NWAY];
#pragma unroll
        for (int hh = 0; hh < HEADS; hh++)
#pragma unroll
            for (int n = 0; n < NWAY; n++) c_r[hh][n] = c_sm[hh][n];

        float4 bo = *reinterpret_cast<const float4*>(b_out + d4);
        float4 acc[NWAY];
#pragma unroll
        for (int n = 0; n < NWAY; n++) acc[n] = bo;

        const __half* Gq = G + (size_t)q * HEADS * DDIM;
#pragma unroll
        for (int hh = 0; hh < HEADS; hh++) {
            uint2 gv = *reinterpret_cast<const uint2*>(Gq + hh * DDIM + d4);
            __half2 p0 = *reinterpret_cast<__half2*>(&gv.x);
            __half2 p1 = *reinterpret_cast<__half2*>(&gv.y);
            float g0 = __low2float(p0), g1 = __high2float(p0);
            float g2 = __low2float(p1), g3 = __high2float(p1);
#pragma unroll
            for (int n = 0; n < NWAY; n++) {
                acc[n].x += c_r[hh][n] * g0;
                acc[n].y += c_r[hh][n] * g1;
                acc[n].z += c_r[hh][n] * g2;
                acc[n].w += c_r[hh][n] * g3;
            }
        }
        float* oq = out + (size_t)q * NWAY * DDIM + d4;
#pragma unroll
        for (int n = 0; n < NWAY; n++)
            *reinterpret_cast<float4*>(oq + n * DDIM) = acc[n];
    }
}

// ---------------------------------------------------------------------------
extern "C" void kernel_launch(void* const* d_in, const int* in_sizes, int n_in,
                              void* d_out, int out_size)
{
    const float* q      = (const float*)d_in[0];
    const float* k      = (const float*)d_in[1];
    const float* v      = (const float*)d_in[2];
    const float* ln_g   = (const float*)d_in[3];
    const float* ln_b   = (const float*)d_in[4];
    const float* W_in   = (const float*)d_in[5];
    const float* W_out  = (const float*)d_in[6];
    const float* b_out  = (const float*)d_in[7];
    const float* vscale = (const float*)d_in[8];
    const float* cscale = (const float*)d_in[9];
    float* out = (float*)d_out;

    float *fk, *R, *kst;
    __half *qhh, *qhl, *khh, *khl, *vhf, *fvh, *G, *wifh, *wifl, *wof;
    cudaGetSymbolAddress((void**)&fk,   g_fk);
    cudaGetSymbolAddress((void**)&R,    g_R);
    cudaGetSymbolAddress((void**)&kst,  g_kst);
    cudaGetSymbolAddress((void**)&qhh,  g_qhh);
    cudaGetSymbolAddress((void**)&qhl,  g_qhl);
    cudaGetSymbolAddress((void**)&khh,  g_khh);
    cudaGetSymbolAddress((void**)&khl,  g_khl);
    cudaGetSymbolAddress((void**)&vhf,  g_vhf);
    cudaGetSymbolAddress((void**)&fvh,  g_fvh);
    cudaGetSymbolAddress((void**)&G,    g_G);
    cudaGetSymbolAddress((void**)&wifh, g_wi_fh);
    cudaGetSymbolAddress((void**)&wifl, g_wi_fl);
    cudaGetSymbolAddress((void**)&wof,  g_wo_f);

    const int SMEM = 2 * 98304 + 128;   // 196736 (2-stage, 96KB/stage MODE1)
    cudaFuncSetAttribute((const void*)kv_gemm_kernel,
                         cudaFuncAttributeMaxDynamicSharedMemorySize, SMEM);
    cudaFuncSetAttribute((const void*)qg_gemm_kernel,
                         cudaFuncAttributeMaxDynamicSharedMemorySize, SMEM);

    // 1) fused LN (vectorized) + weight prep in one launch
    prep_all_kernel<<<LN_BLOCKS + WP_BLOCKS, 256>>>(
        q, k, v, ln_g, ln_b, qhh, qhl, khh, khl, vhf,
        W_in, W_out, wifh, wifl, wof);

    // 2) k-projection (+ fused k-stats) and v-projection in one launch
    kv_gemm_kernel<<<256, 256, SMEM>>>(
        khh, khl, wifh, wifl, fk, kst, vhf, fvh);

    // 3) q-projection (+ fused combine reductions) and A-reuse G in one launch
    qg_gemm_kernel<<<1152, 256, SMEM>>>(
        qhh, qhl, wifh, wifl, fk, R, fvh, wof, G);

    // 4) fused combine + output assembly (register n-reuse, no G staging)
    combine_out_kernel<<<QLEN, 256>>>(R, kst, G, vscale, cscale, b_out, out);
}